// round 13
// baseline (speedup 1.0000x reference)
#include <cuda_runtime.h>
#include <cstdint>
#include <math.h>

#define TOKENS 16384
#define KDIM   2048
#define NEXP   64
#define TM     64                      // tokens per CTA -> grid 256
#define KC     64                      // K elems per chunk
#define NCHUNK (KDIM / KC)             // 32
#define NITER  (NCHUNK / 2)            // 16 (2 chunks per barrier)
#define SA     144                     // smem row stride bytes (conflict-free ldmatrix)
#define OFF_B  (64 * SA)               // 9216
#define STAGE  (2 * 64 * SA)           // 18432 per stage (A + B)
#define NSTAGE 4
#define DYN_SMEM (NSTAGE * STAGE)      // 73728 -> 2 CTAs/SM
#define RESCUE_TH 2.5e-3f

typedef unsigned int u32;

// Pre-converted W fp16 plane (pairs packed in u32), refreshed every call.
__device__ __align__(16) u32 g_Wh[NEXP * KDIM / 2];

// ---------------- helpers ----------------
static __device__ __forceinline__ u32 smem_u32(const void* p) {
    u32 a;
    asm("{ .reg .u64 t; cvta.to.shared.u64 t, %1; cvt.u32.u64 %0, t; }" : "=r"(a) : "l"(p));
    return a;
}
static __device__ __forceinline__ u32 cvt_h2(float f0, float f1) {
    u32 r;
    asm("cvt.rn.f16x2.f32 %0, %1, %2;" : "=r"(r) : "f"(f1), "f"(f0));
    return r;
}
static __device__ __forceinline__ void sts128(u32 a, u32 v0, u32 v1, u32 v2, u32 v3) {
    asm volatile("st.shared.v4.b32 [%0], {%1,%2,%3,%4};"
                 :: "r"(a), "r"(v0), "r"(v1), "r"(v2), "r"(v3) : "memory");
}
static __device__ __forceinline__ void cpasync16(u32 dst, const void* src) {
    asm volatile("cp.async.cg.shared.global [%0], [%1], 16;" :: "r"(dst), "l"(src) : "memory");
}
#define CP_COMMIT() asm volatile("cp.async.commit_group;" ::: "memory")
#define CP_WAIT0()  asm volatile("cp.async.wait_group 0;" ::: "memory")
static __device__ __forceinline__ void ldm_x4(u32* r, u32 a) {
    asm volatile("ldmatrix.sync.aligned.m8n8.x4.shared.b16 {%0,%1,%2,%3}, [%4];"
                 : "=r"(r[0]), "=r"(r[1]), "=r"(r[2]), "=r"(r[3]) : "r"(a));
}
static __device__ __forceinline__ void mma_f16(float* c, const u32* a, u32 b0, u32 b1) {
    asm volatile("mma.sync.aligned.m16n8k16.row.col.f32.f16.f16.f32 "
                 "{%0,%1,%2,%3}, {%4,%5,%6,%7}, {%8,%9}, {%0,%1,%2,%3};"
                 : "+f"(c[0]), "+f"(c[1]), "+f"(c[2]), "+f"(c[3])
                 : "r"(a[0]), "r"(a[1]), "r"(a[2]), "r"(a[3]), "r"(b0), "r"(b1));
}

// ---------------- W fp16 prep kernel ----------------
__global__ void prep_w(const float* __restrict__ W) {
    int p = blockIdx.x * blockDim.x + threadIdx.x;   // pair index, 65536 total
    float2 xy = ((const float2*)W)[p];
    g_Wh[p] = cvt_h2(xy.x, xy.y);
}

// ---------------- warp-cooperative exact fp32 dot ----------------
static __device__ __forceinline__ float warp_dot(const float4* __restrict__ xr4,
                                                 const float4* __restrict__ wr4,
                                                 int lane) {
    float a0 = 0.f, a1 = 0.f, a2 = 0.f, a3 = 0.f;
#pragma unroll
    for (int i = 0; i < 16; i++) {
        float4 xv = __ldg(xr4 + lane + 32 * i);
        float4 wv = __ldg(wr4 + lane + 32 * i);
        a0 = fmaf(xv.x, wv.x, a0);
        a1 = fmaf(xv.y, wv.y, a1);
        a2 = fmaf(xv.z, wv.z, a2);
        a3 = fmaf(xv.w, wv.w, a3);
    }
    float s = (a0 + a1) + (a2 + a3);
#pragma unroll
    for (int o = 16; o > 0; o >>= 1)
        s += __shfl_xor_sync(0xffffffffu, s, o);
    return s;
}

// ---------------- main kernel ----------------
__global__ __launch_bounds__(256, 2)
void router_mma(const float* __restrict__ x,
                const float* __restrict__ W,
                const float* __restrict__ bias,
                float* __restrict__ out)
{
    extern __shared__ __align__(16) char dsmp[];
    const u32 sb = smem_u32(dsmp);
    __shared__ float s_bias[NEXP];
    __shared__ int   s_cnt;
    __shared__ int   s_list[TM];
    __shared__ float s_thr[TM];

    const int tid  = threadIdx.x;
    const int wid  = tid >> 5;
    const int lane = tid & 31;
    const int wm   = wid & 1;          // M block (32 tokens)
    const int wn   = wid >> 1;         // expert group (16 experts)
    const int tokBase = blockIdx.x * TM;

    if (tid < NEXP) s_bias[tid] = bias[tid];
    if (tid == 0) s_cnt = 0;

    float acc[2][2][4];
#pragma unroll
    for (int i = 0; i < 2; i++)
#pragma unroll
        for (int j = 0; j < 2; j++)
#pragma unroll
            for (int q = 0; q < 4; q++) acc[i][j][q] = 0.f;

    float4 px0[4], px1[4];             // x regs: px0 = even chunk, px1 = odd chunk
    const float4* xp  = (const float4*)x;
    const uint4*  whp = (const uint4*)g_Wh;

    const int xrow = tid >> 3, xc8 = tid & 7;   // x: rows tid>>3, +32; 2 float4 each
    const int brow = tid >> 3, bc16 = tid & 7;  // B: rows tid>>3, +32

#define LOAD_PX(P, c)                                                               \
    do {                                                                            \
        _Pragma("unroll")                                                           \
        for (int r = 0; r < 2; r++) {                                               \
            const float4* src = xp + (size_t)(tokBase + xrow + 32 * r) * (KDIM / 4) \
                                   + (c) * 16 + xc8 * 2;                            \
            P[2 * r]     = src[0];                                                  \
            P[2 * r + 1] = src[1];                                                  \
        }                                                                           \
    } while (0)

#define ISSUE_B1(c, st)                                                             \
    do {                                                                            \
        _Pragma("unroll")                                                           \
        for (int r = 0; r < 2; r++) {                                               \
            int row = brow + r * 32;                                                \
            cpasync16(sb + (u32)(st) * STAGE + OFF_B + (u32)(row * SA + bc16 * 16), \
                      whp + row * (KDIM / 8) + (c) * 8 + bc16);                     \
        }                                                                           \
    } while (0)

#define STS_A(P, st)                                                                \
    do {                                                                            \
        _Pragma("unroll")                                                           \
        for (int r = 0; r < 2; r++) {                                               \
            u32 a = sb + (u32)(st) * STAGE + (u32)((xrow + 32 * r) * SA + xc8 * 16);\
            float4 v0 = P[2 * r], v1 = P[2 * r + 1];                                \
            sts128(a, cvt_h2(v0.x, v0.y), cvt_h2(v0.z, v0.w),                       \
                      cvt_h2(v1.x, v1.y), cvt_h2(v1.z, v1.w));                      \
        }                                                                           \
    } while (0)

    // consumer base offsets (stage-relative, R4/R10-verified mappings)
    const u32 aOff = (u32)((wm * 32 + (lane & 15)) * SA + (lane >> 4) * 16);
    const u32 bOff = (u32)(OFF_B + (wn * 16 + ((lane >> 4) & 1) * 8 + (lane & 7)) * SA +
                           ((lane >> 3) & 1) * 16);

#define COMPUTE1(st)                                                                \
    do {                                                                            \
        const u32 aAddr = sb + (u32)(st) * STAGE + aOff;                            \
        const u32 bAddr = sb + (u32)(st) * STAGE + bOff;                            \
        _Pragma("unroll")                                                           \
        for (int ks = 0; ks < 4; ks++) {                                            \
            u32 A[2][4], B[4];                                                      \
            ldm_x4(A[0], aAddr + ks * 32);                                          \
            ldm_x4(A[1], aAddr + 16 * SA + ks * 32);                                \
            ldm_x4(B, bAddr + ks * 32);                                             \
            _Pragma("unroll")                                                       \
            for (int mt = 0; mt < 2; mt++) {                                        \
                mma_f16(acc[mt][0], A[mt], B[0], B[1]);                             \
                mma_f16(acc[mt][1], A[mt], B[2], B[3]);                             \
            }                                                                       \
        }                                                                           \
    } while (0)

    // ---------------- prologue ----------------
    ISSUE_B1(0, 0);
    ISSUE_B1(1, 1);
    CP_COMMIT();                       // group {B0,B1}
    LOAD_PX(px0, 0);
    LOAD_PX(px1, 1);
    STS_A(px0, 0);                     // waits on px0 DRAM latency once
    STS_A(px1, 1);
    LOAD_PX(px0, 2);
    LOAD_PX(px1, 3);

    // ---------------- main loop: 16 iters, 2 chunks each ----------------
#pragma unroll 2
    for (int i = 0; i < NITER; i++) {
        const int s0 = (2 * i) % 4;        // compute stages this iter
        const int s1 = s0 + 1;
        const int t0 = (2 * i + 2) % 4;    // stages to refill
        const int t1 = t0 + 1;

        CP_WAIT0();                        // B(2i), B(2i+1) landed
        __syncthreads();                   // stages t0,t1 free; A(2i..2i+1)+B visible

        if (i + 1 < NITER) {
            ISSUE_B1(2 * i + 2, t0);
            ISSUE_B1(2 * i + 3, t1);
            CP_COMMIT();
            STS_A(px0, t0);                // px0/px1 hold chunks 2i+2 / 2i+3 (landed)
            STS_A(px1, t1);
        }
        if (i + 2 < NITER) {
            LOAD_PX(px0, 2 * i + 4);
            LOAD_PX(px1, 2 * i + 5);
        }

        COMPUTE1(s0);
        COMPUTE1(s1);
    }

    // ---------------- epilogue ----------------
    __syncthreads();
    float* ls = (float*)dsmp;            // logits staging [64][65] = 16.6 KB
#pragma unroll
    for (int mt = 0; mt < 2; mt++)
#pragma unroll
        for (int nt = 0; nt < 2; nt++) {
            const int row = wm * 32 + mt * 16 + (lane >> 2);
            const int col = wn * 16 + nt * 8 + (lane & 3) * 2;
            ls[row * 65 + col]           = acc[mt][nt][0] + s_bias[col];
            ls[row * 65 + col + 1]       = acc[mt][nt][1] + s_bias[col + 1];
            ls[(row + 8) * 65 + col]     = acc[mt][nt][2] + s_bias[col];
            ls[(row + 8) * 65 + col + 1] = acc[mt][nt][3] + s_bias[col + 1];
        }
    __syncthreads();

    float* probs_out  = out;
    float* idx_out    = out + (size_t)TOKENS * 2;
    float* logits_out = out + (size_t)TOKENS * 4;

    // coalesced logits store: 1024 float4 per block, 4 per thread
#pragma unroll
    for (int r = 0; r < 4; r++) {
        int s  = tid + 256 * r;
        int t  = s >> 4;
        int e4 = s & 15;
        const float* lr = &ls[t * 65 + e4 * 4];
        *(float4*)(logits_out + (size_t)(tokBase + t) * NEXP + e4 * 4) =
            make_float4(lr[0], lr[1], lr[2], lr[3]);
    }

    // per-token top-2; near-ties enqueued for warp-parallel exact rescue
    if (tid < TM) {
        const int t = tid;
        const int gt = tokBase + t;
        const float* lr = &ls[t * 65];
        float m1 = -INFINITY, m2 = -INFINITY, m3 = -INFINITY;
        int i1 = 0, i2 = 0;
#pragma unroll
        for (int e = 0; e < NEXP; e++) {
            const float v = lr[e];
            if (v > m1)      { m3 = m2; m2 = m1; i2 = i1; m1 = v; i1 = e; }
            else if (v > m2) { m3 = m2; m2 = v; i2 = e; }
            else if (v > m3) { m3 = v; }
        }

        if ((m1 - m2 < RESCUE_TH) || (m2 - m3 < RESCUE_TH)) {
            int j = atomicAdd(&s_cnt, 1);
            s_list[j] = t;
            s_thr[t]  = m2 - RESCUE_TH;
        } else {
            const float ex2 = expf(m2 - m1);
            const float inv = 1.0f / (1.0f + ex2);
            probs_out[gt * 2 + 0] = inv;
            probs_out[gt * 2 + 1] = ex2 * inv;
            idx_out[gt * 2 + 0] = (float)i1;
            idx_out[gt * 2 + 1] = (float)i2;
        }
    }
    __syncthreads();

    // warp-parallel exact rescue
    const int cnt = s_cnt;
    for (int j = wid; j < cnt; j += 8) {
        const int t  = s_list[j];
        const int gt = tokBase + t;
        const float thr = s_thr[t];
        const float* lr = &ls[t * 65];
        const float4* xr4 = (const float4*)(x + (size_t)gt * KDIM);

        float e1 = -INFINITY, e2 = -INFINITY;
        int j1 = 0, j2 = 0;
        for (int e = 0; e < NEXP; e++) {          // ascending: jax first-index tie-break
            if (lr[e] > thr) {
                const float4* wr4 = (const float4*)(W + (size_t)e * KDIM);
                float ex = warp_dot(xr4, wr4, lane) + s_bias[e];
                if (ex > e1)      { e2 = e1; j2 = j1; e1 = ex; j1 = e; }
                else if (ex > e2) { e2 = ex; j2 = e; }
            }
        }
        if (lane == 0) {
            const float ex2 = expf(e2 - e1);
            const float inv = 1.0f / (1.0f + ex2);
            probs_out[gt * 2 + 0] = inv;
            probs_out[gt * 2 + 1] = ex2 * inv;
            idx_out[gt * 2 + 0] = (float)j1;
            idx_out[gt * 2 + 1] = (float)j2;
        }
    }
}

extern "C" void kernel_launch(void* const* d_in, const int* in_sizes, int n_in,
                              void* d_out, int out_size)
{
    const float* x = (const float*)d_in[0];
    const float* W = (const float*)d_in[1];
    const float* b = (const float*)d_in[2];
    float* out = (float*)d_out;

    cudaFuncSetAttribute(router_mma, cudaFuncAttributeMaxDynamicSharedMemorySize, DYN_SMEM);
    prep_w<<<256, 256>>>(W);
    router_mma<<<TOKENS / TM, 256, DYN_SMEM>>>(x, W, b, out);
}